// round 4
// baseline (speedup 1.0000x reference)
#include <cuda_runtime.h>
#include <cstdint>

// ---------------- problem constants ----------------
#define T_SIZE 32768
#define TMASK  32767u
#define P1 2654435761u
#define P2 805459861u
#define MAXN (1 << 20)
#define BLK 256

// scratch: compacted active points (no cudaMalloc allowed)
__device__ float4 g_pts[MAXN];
__device__ int    g_count;

// ---------------- kernel 1: mask + defaults + compaction ----------------
__global__ void k_mask_compact(const float* __restrict__ xyz,
                               const float* __restrict__ bmin,
                               const float* __restrict__ bmax,
                               float* __restrict__ out, int N)
{
    int i = blockIdx.x * blockDim.x + threadIdx.x;
    bool inb = false;
    float cx = 0.f, cy = 0.f, cz = 0.f;

    if (i < N) {
        float bx0 = bmin[0], by0 = bmin[1], bz0 = bmin[2];
        float bx1 = bmax[0], by1 = bmax[1], bz1 = bmax[2];
        float x = xyz[3 * i + 0];
        float y = xyz[3 * i + 1];
        float z = xyz[3 * i + 2];
        cx = (x - bx0) / (bx1 - bx0);
        cy = (y - by0) / (by1 - by0);
        cz = (z - bz0) / (bz1 - bz0);
        inb = (cx >= 0.f) & (cx <= 1.f) &
              (cy >= 0.f) & (cy <= 1.f) &
              (cz >= 0.f) & (cz <= 1.f);

        out[i] = inb ? 1.f : 0.f;
        float* dxyz = out + N;
        float* drot = out + (size_t)4 * N;
        dxyz[3 * i + 0] = 0.f;
        dxyz[3 * i + 1] = 0.f;
        dxyz[3 * i + 2] = 0.f;
        drot[4 * i + 0] = 1.f;
        drot[4 * i + 1] = 0.f;
        drot[4 * i + 2] = 0.f;
        drot[4 * i + 3] = 0.f;
    }

    unsigned m = __ballot_sync(0xffffffffu, inb);
    if (inb) {
        int lane = threadIdx.x & 31;
        int leader = __ffs(m) - 1;
        int base = 0;
        if (lane == leader) base = atomicAdd(&g_count, __popc(m));
        base = __shfl_sync(m, base, leader);
        int slot = base + __popc(m & ((1u << lane) - 1u));
        cx = fminf(fmaxf(cx, 0.f), 1.f);
        cy = fminf(fmaxf(cy, 0.f), 1.f);
        cz = fminf(fmaxf(cz, 0.f), 1.f);
        g_pts[slot] = make_float4(cx, cy, cz, __int_as_float(i));
    }
}

// ---------------- smem layout (float offsets) ----------------
// Half-matrices; B-halves offset +16B mod 128B vs A-halves (bank stagger).
#define OW0A 0        // w0 cols  0-31 : [64][32]
#define OW0B 2052     // w0 cols 32-63   (byte 8208 %128 = 16)
#define OW1A 4128     // w1 cols  0-31   (byte 16512 %128 = 0)
#define OW1B 6180     // w1 cols 32-63   (byte 24720 %128 = 16)
#define OW2A 8256     // w2 rows  0-31 : [32][8]
#define OW2B 8516     // w2 rows 32-63   (byte 34064 %128 = 16)
#define OACT 8800     // act exchange: [64][BLK]
#define SMEM_FLOATS (OACT + 64 * BLK)
#define SMEM_BYTES  (SMEM_FLOATS * 4)   // 100736

// ---------------- kernel 2: encode + pair-cooperative MLP ----------------
__global__ __launch_bounds__(BLK, 2)
void k_encode_mlp(const float* __restrict__ table,
                  const float* __restrict__ w0,
                  const float* __restrict__ w1,
                  const float* __restrict__ w2,
                  float* __restrict__ out, int N)
{
    extern __shared__ float sf[];
    int tid = threadIdx.x;

    // stage weights split into halves (one-time)
    for (int idx = tid; idx < 4096; idx += BLK) {
        int i = idx >> 6, j = idx & 63;
        int dst = (j < 32) ? (OW0A + i * 32 + j) : (OW0B + i * 32 + j - 32);
        sf[dst] = w0[idx];
        int dst1 = (j < 32) ? (OW1A + i * 32 + j) : (OW1B + i * 32 + j - 32);
        sf[dst1] = w1[idx];
    }
    for (int idx = tid; idx < 512; idx += BLK) {
        int i = idx >> 3, j = idx & 7;
        int dst = (i < 32) ? (OW2A + i * 8 + j) : (OW2B + (i - 32) * 8 + j);
        sf[dst] = w2[idx];
    }
    __syncthreads();

    int cnt = g_count;
    int ntiles = (cnt + BLK - 1) / BLK;
    if ((int)blockIdx.x >= ntiles) return;

    int half = tid & 1;
    const float4* myw0 = (const float4*)(sf + (half ? OW0B : OW0A));
    const float4* myw1 = (const float4*)(sf + (half ? OW1B : OW1A));
    const float4* myw2 = (const float4*)(sf + (half ? OW2B : OW2A));
    float* acol = sf + OACT + (tid & ~1);   // pair's column (8B aligned)
    int prow = half ? 32 : 0;

    const float4* tbl = (const float4*)table;
    float* dxyz = out + N;
    float* drot = out + (size_t)4 * N;

    for (int tile = blockIdx.x; tile < ntiles; tile += gridDim.x) {
        int slot = tile * BLK + tid;
        bool act = slot < cnt;
        float4 p = act ? g_pts[slot] : make_float4(0.f, 0.f, 0.f, 0.f);
        float cx = p.x, cy = p.y, cz = p.z;
        int ipt = __float_as_int(p.w);

        // hP0: accum for pair's even point; hP1: odd point. This lane's
        // 32-output half (prow..prow+31) of layer 1.
        float hP0[32], hP1[32];
        #pragma unroll
        for (int j = 0; j < 32; j++) { hP0[j] = 0.f; hP1[j] = 0.f; }

        // ---- encode (own point) fused with layer-1 (both points) ----
        float sc = 16.f;
        #pragma unroll 1
        for (int l = 0; l < 16; l++) {
            float a0 = 0.f, a1 = 0.f, a2 = 0.f, a3 = 0.f;
            if (act) {
                float px = cx * sc, py = cy * sc, pz = cz * sc;
                float fx = floorf(px), fy = floorf(py), fz = floorf(pz);
                float tx = px - fx, ty = py - fy, tz = pz - fz;
                unsigned ux = (unsigned)fx, uy = (unsigned)fy, uz = (unsigned)fz;
                unsigned hx0 = ux,      hx1 = ux + 1u;
                unsigned hy0 = uy * P1, hy1 = hy0 + P1;
                unsigned hz0 = uz * P2, hz1 = hz0 + P2;
                unsigned base = (unsigned)l * T_SIZE;
                float wxv[2] = {1.f - tx, tx};
                float wyv[2] = {1.f - ty, ty};
                float wzv[2] = {1.f - tz, tz};
                #pragma unroll
                for (int c = 0; c < 8; c++) {
                    unsigned hx = (c & 4) ? hx1 : hx0;
                    unsigned hy = (c & 2) ? hy1 : hy0;
                    unsigned hz = (c & 1) ? hz1 : hz0;
                    unsigned idx = (hx ^ hy ^ hz) & TMASK;
                    float4 f = __ldg(tbl + (base + idx));
                    float w = wxv[(c >> 2) & 1] * wyv[(c >> 1) & 1] * wzv[c & 1];
                    a0 += w * f.x; a1 += w * f.y; a2 += w * f.z; a3 += w * f.w;
                }
            }
            // exchange enc features with pair partner
            float b0 = __shfl_xor_sync(0xffffffffu, a0, 1);
            float b1 = __shfl_xor_sync(0xffffffffu, a1, 1);
            float b2 = __shfl_xor_sync(0xffffffffu, a2, 1);
            float b3 = __shfl_xor_sync(0xffffffffu, a3, 1);
            // order as (even point, odd point)
            float e0 = half ? b0 : a0, q0 = half ? a0 : b0;
            float e1 = half ? b1 : a1, q1 = half ? a1 : b1;
            float e2 = half ? b2 : a2, q2 = half ? a2 : b2;
            float e3 = half ? b3 : a3, q3 = half ? a3 : b3;
            float ev[4] = {e0, e1, e2, e3};
            float qv[4] = {q0, q1, q2, q3};

            const float4* wr = myw0 + (l * 4) * 8;
            #pragma unroll
            for (int f = 0; f < 4; f++) {
                float u = ev[f], v = qv[f];
                #pragma unroll
                for (int jj = 0; jj < 8; jj++) {
                    float4 w4 = wr[f * 8 + jj];
                    hP0[4*jj+0] += u * w4.x; hP1[4*jj+0] += v * w4.x;
                    hP0[4*jj+1] += u * w4.y; hP1[4*jj+1] += v * w4.y;
                    hP0[4*jj+2] += u * w4.z; hP1[4*jj+2] += v * w4.z;
                    hP0[4*jj+3] += u * w4.w; hP1[4*jj+3] += v * w4.w;
                }
            }
            sc *= 2.f;
        }

        // relu + spill this lane's half for both points (float2 per row)
        #pragma unroll
        for (int j = 0; j < 32; j++) {
            float2 s;
            s.x = fmaxf(hP0[j], 0.f);
            s.y = fmaxf(hP1[j], 0.f);
            *(float2*)(acol + (prow + j) * BLK) = s;
        }
        __syncwarp();

        // ---- layer 2: both points, this lane's 32-out half ----
        #pragma unroll
        for (int j = 0; j < 32; j++) { hP0[j] = 0.f; hP1[j] = 0.f; }
        #pragma unroll 4
        for (int i = 0; i < 64; i++) {
            float2 v = *(const float2*)(acol + i * BLK);
            const float4* wr = myw1 + i * 8;
            #pragma unroll
            for (int jj = 0; jj < 8; jj++) {
                float4 w4 = wr[jj];
                hP0[4*jj+0] += v.x * w4.x; hP1[4*jj+0] += v.y * w4.x;
                hP0[4*jj+1] += v.x * w4.y; hP1[4*jj+1] += v.y * w4.y;
                hP0[4*jj+2] += v.x * w4.z; hP1[4*jj+2] += v.y * w4.z;
                hP0[4*jj+3] += v.x * w4.w; hP1[4*jj+3] += v.y * w4.w;
            }
        }
        __syncwarp();   // sact reads done before next tile's spill

        // ---- layer 3: partial 8 outs per point from this lane's 32 ins ----
        float o0[8], o1[8];
        #pragma unroll
        for (int k = 0; k < 8; k++) { o0[k] = 0.f; o1[k] = 0.f; }
        #pragma unroll 8
        for (int j = 0; j < 32; j++) {
            float vp = fmaxf(hP0[j], 0.f);
            float vq = fmaxf(hP1[j], 0.f);
            float4 wa = myw2[j * 2];
            float4 wb = myw2[j * 2 + 1];
            o0[0] += vp * wa.x; o0[1] += vp * wa.y;
            o0[2] += vp * wa.z; o0[3] += vp * wa.w;
            o0[4] += vp * wb.x; o0[5] += vp * wb.y;
            o0[6] += vp * wb.z; o0[7] += vp * wb.w;
            o1[0] += vq * wa.x; o1[1] += vq * wa.y;
            o1[2] += vq * wa.z; o1[3] += vq * wa.w;
            o1[4] += vq * wb.x; o1[5] += vq * wb.y;
            o1[6] += vq * wb.z; o1[7] += vq * wb.w;
        }
        // pair reduction (only 7 outputs used)
        #pragma unroll
        for (int k = 0; k < 7; k++) {
            o0[k] += __shfl_xor_sync(0xffffffffu, o0[k], 1);
            o1[k] += __shfl_xor_sync(0xffffffffu, o1[k], 1);
        }

        if (act) {
            float r0 = half ? o1[0] : o0[0];
            float r1 = half ? o1[1] : o0[1];
            float r2 = half ? o1[2] : o0[2];
            float r3 = half ? o1[3] : o0[3];
            float r4 = half ? o1[4] : o0[4];
            float r5 = half ? o1[5] : o0[5];
            float r6 = half ? o1[6] : o0[6];
            dxyz[3 * ipt + 0] = r0;
            dxyz[3 * ipt + 1] = r1;
            dxyz[3 * ipt + 2] = r2;
            drot[4 * ipt + 0] = r3;
            drot[4 * ipt + 1] = r4;
            drot[4 * ipt + 2] = r5;
            drot[4 * ipt + 3] = r6;
        }
    }
}

// ---------------- launch ----------------
extern "C" void kernel_launch(void* const* d_in, const int* in_sizes, int n_in,
                              void* d_out, int out_size)
{
    const float* xyz   = (const float*)d_in[0];
    const float* bmin  = (const float*)d_in[1];
    const float* bmax  = (const float*)d_in[2];
    const float* table = (const float*)d_in[3];
    const float* w0    = (const float*)d_in[4];
    const float* w1    = (const float*)d_in[5];
    const float* w2    = (const float*)d_in[6];
    int N = in_sizes[0] / 3;
    float* out = (float*)d_out;

    void* cptr = nullptr;
    cudaGetSymbolAddress(&cptr, g_count);
    cudaMemsetAsync(cptr, 0, sizeof(int), 0);

    int grid1 = (N + 255) / 256;
    k_mask_compact<<<grid1, 256>>>(xyz, bmin, bmax, out, N);

    cudaFuncSetAttribute(k_encode_mlp,
                         cudaFuncAttributeMaxDynamicSharedMemorySize, SMEM_BYTES);
    int grid2 = 296;  // 2 blocks/SM, persistent grid-stride
    k_encode_mlp<<<grid2, BLK, SMEM_BYTES>>>(table, w0, w1, w2, out, N);
}

// round 5
// speedup vs baseline: 1.4994x; 1.4994x over previous
#include <cuda_runtime.h>
#include <cstdint>

// ---------------- problem constants ----------------
#define L_LEVELS 16
#define T_SIZE   32768
#define TMASK    32767u
#define P1 2654435761u
#define P2 805459861u
#define BLOCK2 128
#define MAXN (1 << 20)
#define NBINS 32768

// scratch (no cudaMalloc allowed)
__device__ float4 g_tmp[MAXN];    // compacted, unsorted
__device__ float4 g_pts[MAXN];    // morton-sorted
__device__ unsigned g_keys[MAXN];
__device__ int g_hist[NBINS];
__device__ int g_off[NBINS];
__device__ int g_count;

__device__ __forceinline__ unsigned part5(unsigned x) {
    // spread 5 bits to every 3rd position
    return ((x & 16u) << 8) | ((x & 8u) << 6) | ((x & 4u) << 4) |
           ((x & 2u) << 2) | (x & 1u);
}

// ---------------- kernel 1: mask + defaults + compact + histogram ------
__global__ void k_mask_compact(const float* __restrict__ xyz,
                               const float* __restrict__ bmin,
                               const float* __restrict__ bmax,
                               float* __restrict__ out, int N)
{
    int i = blockIdx.x * blockDim.x + threadIdx.x;
    bool inb = false;
    float cx = 0.f, cy = 0.f, cz = 0.f;

    if (i < N) {
        float bx0 = bmin[0], by0 = bmin[1], bz0 = bmin[2];
        float bx1 = bmax[0], by1 = bmax[1], bz1 = bmax[2];
        float x = xyz[3 * i + 0];
        float y = xyz[3 * i + 1];
        float z = xyz[3 * i + 2];
        cx = (x - bx0) / (bx1 - bx0);
        cy = (y - by0) / (by1 - by0);
        cz = (z - bz0) / (bz1 - bz0);
        inb = (cx >= 0.f) & (cx <= 1.f) &
              (cy >= 0.f) & (cy <= 1.f) &
              (cz >= 0.f) & (cz <= 1.f);

        out[i] = inb ? 1.f : 0.f;
        float* dxyz = out + N;
        float* drot = out + (size_t)4 * N;
        dxyz[3 * i + 0] = 0.f;
        dxyz[3 * i + 1] = 0.f;
        dxyz[3 * i + 2] = 0.f;
        drot[4 * i + 0] = 1.f;
        drot[4 * i + 1] = 0.f;
        drot[4 * i + 2] = 0.f;
        drot[4 * i + 3] = 0.f;
    }

    unsigned m = __ballot_sync(0xffffffffu, inb);
    if (inb) {
        int lane = threadIdx.x & 31;
        int leader = __ffs(m) - 1;
        int base = 0;
        if (lane == leader) base = atomicAdd(&g_count, __popc(m));
        base = __shfl_sync(m, base, leader);
        int slot = base + __popc(m & ((1u << lane) - 1u));
        cx = fminf(fmaxf(cx, 0.f), 1.f);
        cy = fminf(fmaxf(cy, 0.f), 1.f);
        cz = fminf(fmaxf(cz, 0.f), 1.f);
        g_tmp[slot] = make_float4(cx, cy, cz, __int_as_float(i));
        unsigned qx = min(31u, (unsigned)(cx * 32.f));
        unsigned qy = min(31u, (unsigned)(cy * 32.f));
        unsigned qz = min(31u, (unsigned)(cz * 32.f));
        unsigned key = part5(qx) | (part5(qy) << 1) | (part5(qz) << 2);
        g_keys[slot] = key;
        atomicAdd(&g_hist[key], 1);
    }
}

// ---------------- kernel 1b: exclusive scan over 32768 bins (1 block) ---
__global__ void k_scan()
{
    int tid = threadIdx.x;            // 1024 threads, 32 bins each
    int base = tid * 32;
    int s = 0;
    #pragma unroll
    for (int k = 0; k < 32; k++) s += g_hist[base + k];

    int lane = tid & 31, wid = tid >> 5;
    int v = s;
    #pragma unroll
    for (int d = 1; d < 32; d <<= 1) {
        int t = __shfl_up_sync(0xffffffffu, v, d);
        if (lane >= d) v += t;
    }
    __shared__ int wsum[32];
    if (lane == 31) wsum[wid] = v;
    __syncthreads();
    if (wid == 0) {
        int w = wsum[lane];
        #pragma unroll
        for (int d = 1; d < 32; d <<= 1) {
            int t = __shfl_up_sync(0xffffffffu, w, d);
            if (lane >= d) w += t;
        }
        wsum[lane] = w;
    }
    __syncthreads();
    int excl = v - s + (wid > 0 ? wsum[wid - 1] : 0);
    #pragma unroll
    for (int k = 0; k < 32; k++) {
        int c = g_hist[base + k];
        g_off[base + k] = excl;
        excl += c;
    }
}

// ---------------- kernel 1c: scatter into sorted order ------------------
__global__ void k_scatter()
{
    int cnt = g_count;
    for (int i = blockIdx.x * blockDim.x + threadIdx.x; i < cnt;
         i += gridDim.x * blockDim.x) {
        float4 p = g_tmp[i];
        unsigned key = g_keys[i];
        int pos = atomicAdd(&g_off[key], 1);
        g_pts[pos] = p;
    }
}

// ---------------- kernel 2: hash encode + MLP (R1-proven config) --------
// smem: [w0 4096][w1 4096][w2 512][act 64*BLOCK2]
__global__ __launch_bounds__(BLOCK2, 3)
void k_encode_mlp(const float* __restrict__ table,
                  const float* __restrict__ w0,
                  const float* __restrict__ w1,
                  const float* __restrict__ w2,
                  float* __restrict__ out, int N)
{
    extern __shared__ float sm[];
    float* sw0  = sm;            // 4096 floats
    float* sw1  = sm + 4096;     // 4096 floats
    float* sw2  = sm + 8192;     // 512 floats
    float* sact = sm + 8704;     // 64 * BLOCK2 floats

    int tid = threadIdx.x;
    int cnt = g_count;
    if ((int)(blockIdx.x * BLOCK2) >= cnt) return;

    for (int k = tid; k < 4096 / 4; k += BLOCK2)
        ((float4*)sw0)[k] = ((const float4*)w0)[k];
    for (int k = tid; k < 4096 / 4; k += BLOCK2)
        ((float4*)sw1)[k] = ((const float4*)w1)[k];
    for (int k = tid; k < 512 / 4; k += BLOCK2)
        ((float4*)sw2)[k] = ((const float4*)w2)[k];
    __syncthreads();

    const float4* tbl = (const float4*)table;
    float* dxyz = out + N;
    float* drot = out + (size_t)4 * N;

    for (int slot = blockIdx.x * BLOCK2 + tid; slot < cnt;
         slot += gridDim.x * BLOCK2) {
        float4 p = g_pts[slot];
        float cx = p.x, cy = p.y, cz = p.z;
        int ipt = __float_as_int(p.w);

        float h[64];
        #pragma unroll
        for (int j = 0; j < 64; j++) h[j] = 0.f;

        float sc = 16.f;
        #pragma unroll 1
        for (int l = 0; l < L_LEVELS; l++) {
            float px = cx * sc, py = cy * sc, pz = cz * sc;
            float fx = floorf(px), fy = floorf(py), fz = floorf(pz);
            float tx = px - fx, ty = py - fy, tz = pz - fz;
            unsigned ux = (unsigned)fx, uy = (unsigned)fy, uz = (unsigned)fz;

            unsigned hx0 = ux,        hx1 = ux + 1u;
            unsigned hy0 = uy * P1,   hy1 = hy0 + P1;
            unsigned hz0 = uz * P2,   hz1 = hz0 + P2;
            unsigned base = (unsigned)l * T_SIZE;

            float wx[2] = {1.f - tx, tx};
            float wy[2] = {1.f - ty, ty};
            float wz[2] = {1.f - tz, tz};

            float a0 = 0.f, a1 = 0.f, a2 = 0.f, a3 = 0.f;
            #pragma unroll
            for (int c = 0; c < 8; c++) {
                unsigned hx = (c & 4) ? hx1 : hx0;
                unsigned hy = (c & 2) ? hy1 : hy0;
                unsigned hz = (c & 1) ? hz1 : hz0;
                unsigned idx = (hx ^ hy ^ hz) & TMASK;
                float4 f = __ldg(tbl + (base + idx));
                float w = wx[(c >> 2) & 1] * wy[(c >> 1) & 1] * wz[c & 1];
                a0 += w * f.x; a1 += w * f.y; a2 += w * f.z; a3 += w * f.w;
            }

            float av[4] = {a0, a1, a2, a3};
            #pragma unroll
            for (int f = 0; f < 4; f++) {
                const float4* wr = (const float4*)(sw0 + ((l * 4 + f) << 6));
                float a = av[f];
                #pragma unroll
                for (int jj = 0; jj < 16; jj++) {
                    float4 wv = wr[jj];
                    h[4 * jj + 0] += a * wv.x;
                    h[4 * jj + 1] += a * wv.y;
                    h[4 * jj + 2] += a * wv.z;
                    h[4 * jj + 3] += a * wv.w;
                }
            }
            sc *= 2.f;
        }

        #pragma unroll
        for (int j = 0; j < 64; j++)
            sact[j * BLOCK2 + tid] = fmaxf(h[j], 0.f);

        #pragma unroll
        for (int j = 0; j < 64; j++) h[j] = 0.f;
        #pragma unroll 4
        for (int i = 0; i < 64; i++) {
            float v = sact[i * BLOCK2 + tid];
            const float4* wr = (const float4*)(sw1 + (i << 6));
            #pragma unroll
            for (int jj = 0; jj < 16; jj++) {
                float4 wv = wr[jj];
                h[4 * jj + 0] += v * wv.x;
                h[4 * jj + 1] += v * wv.y;
                h[4 * jj + 2] += v * wv.z;
                h[4 * jj + 3] += v * wv.w;
            }
        }
        #pragma unroll
        for (int j = 0; j < 64; j++)
            sact[j * BLOCK2 + tid] = fmaxf(h[j], 0.f);

        float o[8];
        #pragma unroll
        for (int k = 0; k < 8; k++) o[k] = 0.f;
        #pragma unroll 8
        for (int i = 0; i < 64; i++) {
            float v = sact[i * BLOCK2 + tid];
            const float4* wr = (const float4*)(sw2 + (i << 3));
            float4 wa = wr[0], wb = wr[1];
            o[0] += v * wa.x; o[1] += v * wa.y; o[2] += v * wa.z; o[3] += v * wa.w;
            o[4] += v * wb.x; o[5] += v * wb.y; o[6] += v * wb.z; o[7] += v * wb.w;
        }

        dxyz[3 * ipt + 0] = o[0];
        dxyz[3 * ipt + 1] = o[1];
        dxyz[3 * ipt + 2] = o[2];
        drot[4 * ipt + 0] = o[3];
        drot[4 * ipt + 1] = o[4];
        drot[4 * ipt + 2] = o[5];
        drot[4 * ipt + 3] = o[6];
    }
}

// ---------------- launch ----------------
extern "C" void kernel_launch(void* const* d_in, const int* in_sizes, int n_in,
                              void* d_out, int out_size)
{
    const float* xyz   = (const float*)d_in[0];
    const float* bmin  = (const float*)d_in[1];
    const float* bmax  = (const float*)d_in[2];
    const float* table = (const float*)d_in[3];
    const float* w0    = (const float*)d_in[4];
    const float* w1    = (const float*)d_in[5];
    const float* w2    = (const float*)d_in[6];
    int N = in_sizes[0] / 3;
    float* out = (float*)d_out;

    void* cptr = nullptr;
    cudaGetSymbolAddress(&cptr, g_count);
    cudaMemsetAsync(cptr, 0, sizeof(int), 0);
    void* hptr = nullptr;
    cudaGetSymbolAddress(&hptr, g_hist);
    cudaMemsetAsync(hptr, 0, NBINS * sizeof(int), 0);

    int grid1 = (N + 255) / 256;
    k_mask_compact<<<grid1, 256>>>(xyz, bmin, bmax, out, N);
    k_scan<<<1, 1024>>>();
    k_scatter<<<512, 256>>>();

    int smem = (8704 + 64 * BLOCK2) * (int)sizeof(float);  // 67584 B
    cudaFuncSetAttribute(k_encode_mlp,
                         cudaFuncAttributeMaxDynamicSharedMemorySize, smem);
    k_encode_mlp<<<444, BLOCK2, smem>>>(table, w0, w1, w2, out, N);
}